// round 3
// baseline (speedup 1.0000x reference)
#include <cuda_runtime.h>
#include <math.h>

// NodeConv:
//   xs = [x | gs]  (133)
//   y_neg[n]  = xs[n] @ W_neg[0:133] + b_neg           (per NODE)
//   out[n]    = elu(xs[n] @ W_root + b_root)
//   out[dst] += sum_{e: dst(e)=dst} elu(y_neg[src(e)] + ea[e] @ W_neg[133:139])
//
// Scatter->gather via counting sort by dst. Scatter materializes fat records
// (src, ea[6]) so the gather loop has a single dependent random load per edge.

#define NMAX 100000
#define EMAX 1600000
#define NBMAX ((NMAX + 255) / 256)

__device__ float  g_yneg[(size_t)NMAX * 128];
__device__ float4 g_rec[(size_t)EMAX * 2];     // per-edge: {src,ea0,ea1,ea2},{ea3,ea4,ea5,-}
__device__ int    g_count[NMAX];
__device__ int    g_offset[NMAX + 1];
__device__ int    g_cursor[NMAX];
__device__ int    g_blocksum[NBMAX];
__device__ int    g_blockoff[NBMAX];
__device__ int    g_is64;

__device__ __forceinline__ float eluf(float v) {
    return v > 0.0f ? v : expm1f(v);
}

__device__ __forceinline__ int load_idx(const void* ei, int is64, size_t pos) {
    return is64 ? (int)__ldg((const long long*)ei + pos)
                : __ldg((const int*)ei + pos);
}

// ---------------------------------------------------------------------------
// Prep: block 0 detects int64-vs-int32; all blocks zero g_count.
// ---------------------------------------------------------------------------
__global__ void prep_kernel(const int* __restrict__ ei32, int nwords, int N) {
    if (blockIdx.x == 0) {
        int nz = 0;
        for (int i = 1 + 2 * threadIdx.x; i < min(nwords, 4096); i += 2 * blockDim.x)
            nz |= (ei32[i] != 0);
        int any = __syncthreads_or(nz);
        if (threadIdx.x == 0) g_is64 = any ? 0 : 1;
    }
    for (int i = blockIdx.x * blockDim.x + threadIdx.x; i < N;
         i += gridDim.x * blockDim.x)
        g_count[i] = 0;
}

// ---------------------------------------------------------------------------
// Histogram of dst.
// ---------------------------------------------------------------------------
__global__ void hist_kernel(const void* __restrict__ ei, int E) {
    const int is64 = g_is64;
    int e = blockIdx.x * blockDim.x + threadIdx.x;
    if (e < E) atomicAdd(&g_count[load_idx(ei, is64, e)], 1);
}

// ---------------------------------------------------------------------------
// Scan phase 1: per-block (256) sums of g_count.
// ---------------------------------------------------------------------------
__global__ __launch_bounds__(256)
void scan1_kernel(int N) {
    const int tid = threadIdx.x, lane = tid & 31, w = tid >> 5;
    __shared__ int wsum[8];
    int i = blockIdx.x * 256 + tid;
    int v = (i < N) ? g_count[i] : 0;
#pragma unroll
    for (int o = 16; o > 0; o >>= 1) v += __shfl_down_sync(0xffffffffu, v, o);
    if (lane == 0) wsum[w] = v;
    __syncthreads();
    if (tid == 0) {
        int s = 0;
#pragma unroll
        for (int k = 0; k < 8; k++) s += wsum[k];
        g_blocksum[blockIdx.x] = s;
    }
}

// ---------------------------------------------------------------------------
// Scan phase 2: one block scans the (<=1024) block sums exclusively.
// ---------------------------------------------------------------------------
__global__ __launch_bounds__(1024)
void scan2_kernel(int NB) {
    const int tid = threadIdx.x, lane = tid & 31, w = tid >> 5;
    __shared__ int wtot[32];
    int c = (tid < NB) ? g_blocksum[tid] : 0;
    int v = c;
#pragma unroll
    for (int o = 1; o < 32; o <<= 1) {
        int t = __shfl_up_sync(0xffffffffu, v, o);
        if (lane >= o) v += t;
    }
    if (lane == 31) wtot[w] = v;
    __syncthreads();
    if (w == 0) {
        int s = wtot[lane];
#pragma unroll
        for (int o = 1; o < 32; o <<= 1) {
            int t = __shfl_up_sync(0xffffffffu, s, o);
            if (lane >= o) s += t;
        }
        wtot[lane] = s;
    }
    __syncthreads();
    int excl = ((w == 0) ? 0 : wtot[w - 1]) + v - c;
    if (tid < NB) g_blockoff[tid] = excl;
}

// ---------------------------------------------------------------------------
// Scan phase 3: per-block scan + base -> g_offset / g_cursor.
// ---------------------------------------------------------------------------
__global__ __launch_bounds__(256)
void scan3_kernel(int N, int E) {
    const int tid = threadIdx.x, lane = tid & 31, w = tid >> 5;
    __shared__ int wtot[8];
    int i = blockIdx.x * 256 + tid;
    int c = (i < N) ? g_count[i] : 0;
    int v = c;
#pragma unroll
    for (int o = 1; o < 32; o <<= 1) {
        int t = __shfl_up_sync(0xffffffffu, v, o);
        if (lane >= o) v += t;
    }
    if (lane == 31) wtot[w] = v;
    __syncthreads();
    if (w == 0 && lane < 8) {
        int s = wtot[lane];
#pragma unroll
        for (int o = 1; o < 8; o <<= 1) {
            int t = __shfl_up_sync(0x000000ffu, s, o);
            if (lane >= o) s += t;
        }
        wtot[lane] = s;
    }
    __syncthreads();
    int excl = g_blockoff[blockIdx.x] + ((w == 0) ? 0 : wtot[w - 1]) + v - c;
    if (i < N) {
        g_offset[i] = excl;
        g_cursor[i] = excl;
    }
    if (i == 0) g_offset[N] = E;
}

// ---------------------------------------------------------------------------
// Scatter: build fat CSR records {src, ea[6]}.
// ---------------------------------------------------------------------------
__global__ __launch_bounds__(256)
void scatter_kernel(const void* __restrict__ ei,
                    const float* __restrict__ edge_attr, int E) {
    const int is64 = g_is64;
    int e = blockIdx.x * blockDim.x + threadIdx.x;
    if (e >= E) return;
    int dst = load_idx(ei, is64, e);
    int src = load_idx(ei, is64, (size_t)E + e);
    const float2* ea = (const float2*)(edge_attr + (size_t)e * 6);
    float2 a0 = __ldg(ea + 0);
    float2 a1 = __ldg(ea + 1);
    float2 a2 = __ldg(ea + 2);
    int pos = atomicAdd(&g_cursor[dst], 1);
    g_rec[(size_t)pos * 2]     = make_float4(__int_as_float(src), a0.x, a0.y, a1.x);
    g_rec[(size_t)pos * 2 + 1] = make_float4(a1.y, a2.x, a2.y, 0.0f);
}

// ---------------------------------------------------------------------------
// K1: fused node GEMM. Tile = 64 nodes x 256 outputs (128 y_neg | 128 root).
// ---------------------------------------------------------------------------
__global__ __launch_bounds__(256, 2)
void node_gemm_kernel(const float* __restrict__ x,
                      const float* __restrict__ gs,
                      const float* __restrict__ W_neg,   // [139][128]
                      const float* __restrict__ b_neg,
                      const float* __restrict__ W_root,  // [133][128]
                      const float* __restrict__ b_root,
                      float* __restrict__ out,
                      int N)
{
    __shared__ float As[64][136];
    const int tid = threadIdx.x;
    const int n0 = blockIdx.x * 64;

    for (int i = tid; i < 64 * 133; i += 256) {
        int m = i / 133;
        int k = i - m * 133;
        int n = n0 + m;
        float v = 0.0f;
        if (n < N) v = (k < 128) ? x[(size_t)n * 128 + k]
                                 : gs[(size_t)n * 5 + (k - 128)];
        As[m][k] = v;
    }
    __syncthreads();

    const int c = tid & 31;
    const int r = tid >> 5;
    const bool isRoot = (c >= 16);
    const float* Wsel = isRoot ? W_root : W_neg;
    const float* bsel = isRoot ? b_root : b_neg;
    const int cb = (isRoot ? (c - 16) : c) * 8;

    float acc[8][8];
#pragma unroll
    for (int j = 0; j < 8; j++) {
        float bv = __ldg(bsel + cb + j);
#pragma unroll
        for (int i = 0; i < 8; i++) acc[i][j] = bv;
    }

#pragma unroll 2
    for (int k = 0; k < 133; k++) {
        float4 b0 = __ldg((const float4*)(Wsel + (size_t)k * 128 + cb));
        float4 b1 = __ldg((const float4*)(Wsel + (size_t)k * 128 + cb + 4));
        float a[8];
#pragma unroll
        for (int i = 0; i < 8; i++) a[i] = As[r * 8 + i][k];
#pragma unroll
        for (int i = 0; i < 8; i++) {
            acc[i][0] += a[i] * b0.x;
            acc[i][1] += a[i] * b0.y;
            acc[i][2] += a[i] * b0.z;
            acc[i][3] += a[i] * b0.w;
            acc[i][4] += a[i] * b1.x;
            acc[i][5] += a[i] * b1.y;
            acc[i][6] += a[i] * b1.z;
            acc[i][7] += a[i] * b1.w;
        }
    }

#pragma unroll
    for (int i = 0; i < 8; i++) {
        int n = n0 + r * 8 + i;
        if (n < N) {
            if (isRoot) {
                float4 o0, o1;
                o0.x = eluf(acc[i][0]); o0.y = eluf(acc[i][1]);
                o0.z = eluf(acc[i][2]); o0.w = eluf(acc[i][3]);
                o1.x = eluf(acc[i][4]); o1.y = eluf(acc[i][5]);
                o1.z = eluf(acc[i][6]); o1.w = eluf(acc[i][7]);
                *((float4*)(out + (size_t)n * 128 + cb))     = o0;
                *((float4*)(out + (size_t)n * 128 + cb + 4)) = o1;
            } else {
                *((float4*)(g_yneg + (size_t)n * 128 + cb)) =
                    make_float4(acc[i][0], acc[i][1], acc[i][2], acc[i][3]);
                *((float4*)(g_yneg + (size_t)n * 128 + cb + 4)) =
                    make_float4(acc[i][4], acc[i][5], acc[i][6], acc[i][7]);
            }
        }
    }
}

// ---------------------------------------------------------------------------
// Gather: one warp per node. Records are contiguous per node (streaming);
// the only random access is the y_neg row load, unrolled x4 for MLP.
// ---------------------------------------------------------------------------
__global__ __launch_bounds__(256)
void gather_kernel(const float* __restrict__ W_neg,   // [139][128]
                   float* __restrict__ out, int N)
{
    const int lane  = threadIdx.x & 31;
    const int warp  = blockIdx.x * (blockDim.x >> 5) + (threadIdx.x >> 5);
    const int nwarp = gridDim.x * (blockDim.x >> 5);

    float4 w2[6];
#pragma unroll
    for (int d = 0; d < 6; d++)
        w2[d] = __ldg((const float4*)(W_neg + (size_t)(133 + d) * 128) + lane);

    for (int n = warp; n < N; n += nwarp) {
        const int beg = __ldg(&g_offset[n]);
        const int end = __ldg(&g_offset[n + 1]);
        float4 acc = make_float4(0.f, 0.f, 0.f, 0.f);

        int j = beg;
        for (; j + 4 <= end; j += 4) {
            float4 r0[4], r1[4], v[4];
#pragma unroll
            for (int u = 0; u < 4; u++) {
                r0[u] = __ldg(&g_rec[(size_t)(j + u) * 2]);
                r1[u] = __ldg(&g_rec[(size_t)(j + u) * 2 + 1]);
            }
#pragma unroll
            for (int u = 0; u < 4; u++) {
                int s = __float_as_int(r0[u].x);
                v[u] = __ldg((const float4*)(g_yneg + (size_t)s * 128) + lane);
            }
#pragma unroll
            for (int u = 0; u < 4; u++) {
                v[u].x += r0[u].y * w2[0].x + r0[u].z * w2[1].x + r0[u].w * w2[2].x
                        + r1[u].x * w2[3].x + r1[u].y * w2[4].x + r1[u].z * w2[5].x;
                v[u].y += r0[u].y * w2[0].y + r0[u].z * w2[1].y + r0[u].w * w2[2].y
                        + r1[u].x * w2[3].y + r1[u].y * w2[4].y + r1[u].z * w2[5].y;
                v[u].z += r0[u].y * w2[0].z + r0[u].z * w2[1].z + r0[u].w * w2[2].z
                        + r1[u].x * w2[3].z + r1[u].y * w2[4].z + r1[u].z * w2[5].z;
                v[u].w += r0[u].y * w2[0].w + r0[u].z * w2[1].w + r0[u].w * w2[2].w
                        + r1[u].x * w2[3].w + r1[u].y * w2[4].w + r1[u].z * w2[5].w;
                acc.x += eluf(v[u].x);
                acc.y += eluf(v[u].y);
                acc.z += eluf(v[u].z);
                acc.w += eluf(v[u].w);
            }
        }
        for (; j < end; j++) {
            float4 r0 = __ldg(&g_rec[(size_t)j * 2]);
            float4 r1 = __ldg(&g_rec[(size_t)j * 2 + 1]);
            int s = __float_as_int(r0.x);
            float4 v = __ldg((const float4*)(g_yneg + (size_t)s * 128) + lane);
            v.x += r0.y * w2[0].x + r0.z * w2[1].x + r0.w * w2[2].x
                 + r1.x * w2[3].x + r1.y * w2[4].x + r1.z * w2[5].x;
            v.y += r0.y * w2[0].y + r0.z * w2[1].y + r0.w * w2[2].y
                 + r1.x * w2[3].y + r1.y * w2[4].y + r1.z * w2[5].y;
            v.z += r0.y * w2[0].z + r0.z * w2[1].z + r0.w * w2[2].z
                 + r1.x * w2[3].z + r1.y * w2[4].z + r1.z * w2[5].z;
            v.w += r0.y * w2[0].w + r0.z * w2[1].w + r0.w * w2[2].w
                 + r1.x * w2[3].w + r1.y * w2[4].w + r1.z * w2[5].w;
            acc.x += eluf(v.x);
            acc.y += eluf(v.y);
            acc.z += eluf(v.z);
            acc.w += eluf(v.w);
        }

        float4* o = (float4*)(out + (size_t)n * 128) + lane;
        float4 cur = *o;
        cur.x += acc.x; cur.y += acc.y; cur.z += acc.z; cur.w += acc.w;
        *o = cur;
    }
}

// ---------------------------------------------------------------------------
extern "C" void kernel_launch(void* const* d_in, const int* in_sizes, int n_in,
                              void* d_out, int out_size)
{
    const float* x      = (const float*)d_in[0];
    const void*  ei     = d_in[1];
    const float* eattr  = (const float*)d_in[2];
    const float* gs     = (const float*)d_in[3];
    const float* W_neg  = (const float*)d_in[4];
    const float* b_neg  = (const float*)d_in[5];
    const float* W_root = (const float*)d_in[6];
    const float* b_root = (const float*)d_in[7];
    float* out = (float*)d_out;

    const int N  = in_sizes[0] / 128;   // 100000
    const int E  = in_sizes[2] / 6;     // 1600000
    const int NB = (N + 255) / 256;

    prep_kernel<<<128, 256>>>((const int*)ei, in_sizes[1], N);
    hist_kernel<<<(E + 255) / 256, 256>>>(ei, E);
    scan1_kernel<<<NB, 256>>>(N);
    scan2_kernel<<<1, 1024>>>(NB);
    scan3_kernel<<<NB, 256>>>(N, E);
    scatter_kernel<<<(E + 255) / 256, 256>>>(ei, eattr, E);

    node_gemm_kernel<<<(N + 63) / 64, 256>>>(x, gs, W_neg, b_neg,
                                             W_root, b_root, out, N);

    gather_kernel<<<(N * 32 + 255) / 256, 256>>>(W_neg, out, N);
}

// round 4
// speedup vs baseline: 1.4701x; 1.4701x over previous
#include <cuda_runtime.h>
#include <math.h>

// NodeConv:
//   xs = [x | gs]  (133)
//   y_neg[n]  = xs[n] @ W_neg[0:133] + b_neg           (per NODE)
//   out[n]    = elu(xs[n] @ W_root + b_root)
//   out[dst] += sum_{e: dst(e)=dst} elu(y_neg[src(e)] + ea[e] @ W_neg[133:139])
//
// Counting-sort by dst -> per-node gather, no float atomics.
// Sorted record = int2{src, eid}: 1-deep dependent chain in gather.
// ELU via branchless MUFU path (max(v,0) + __expf(min(v,0)) - 1).

#define NMAX 100000
#define EMAX 1600000
#define NBMAX ((NMAX + 255) / 256)

__device__ float g_yneg[(size_t)NMAX * 128];
__device__ int2  g_se[EMAX];                  // sorted-by-dst: {src, eid}
__device__ int   g_count[NMAX];
__device__ int   g_offset[NMAX + 1];
__device__ int   g_cursor[NMAX];
__device__ int   g_blocksum[NBMAX];
__device__ int   g_blockoff[NBMAX];
__device__ int   g_is64;

// Branchless ELU: exact for v>=0 (__expf(0)==1), ~1e-7 abs err for v<0.
__device__ __forceinline__ float eluf(float v) {
    float neg = fminf(v, 0.0f);
    float pos = fmaxf(v, 0.0f);
    return pos + (__expf(neg) - 1.0f);
}

__device__ __forceinline__ int load_idx(const void* ei, int is64, size_t pos) {
    return is64 ? (int)__ldg((const long long*)ei + pos)
                : __ldg((const int*)ei + pos);
}

// ---------------------------------------------------------------------------
__global__ void prep_kernel(const int* __restrict__ ei32, int nwords, int N) {
    if (blockIdx.x == 0) {
        int nz = 0;
        for (int i = 1 + 2 * threadIdx.x; i < min(nwords, 4096); i += 2 * blockDim.x)
            nz |= (ei32[i] != 0);
        int any = __syncthreads_or(nz);
        if (threadIdx.x == 0) g_is64 = any ? 0 : 1;
    }
    for (int i = blockIdx.x * blockDim.x + threadIdx.x; i < N;
         i += gridDim.x * blockDim.x)
        g_count[i] = 0;
}

// ---------------------------------------------------------------------------
__global__ void hist_kernel(const void* __restrict__ ei, int E) {
    const int is64 = g_is64;
    int e = blockIdx.x * blockDim.x + threadIdx.x;
    if (e < E) atomicAdd(&g_count[load_idx(ei, is64, e)], 1);
}

// ---------------------------------------------------------------------------
__global__ __launch_bounds__(256)
void scan1_kernel(int N) {
    const int tid = threadIdx.x, lane = tid & 31, w = tid >> 5;
    __shared__ int wsum[8];
    int i = blockIdx.x * 256 + tid;
    int v = (i < N) ? g_count[i] : 0;
#pragma unroll
    for (int o = 16; o > 0; o >>= 1) v += __shfl_down_sync(0xffffffffu, v, o);
    if (lane == 0) wsum[w] = v;
    __syncthreads();
    if (tid == 0) {
        int s = 0;
#pragma unroll
        for (int k = 0; k < 8; k++) s += wsum[k];
        g_blocksum[blockIdx.x] = s;
    }
}

__global__ __launch_bounds__(1024)
void scan2_kernel(int NB) {
    const int tid = threadIdx.x, lane = tid & 31, w = tid >> 5;
    __shared__ int wtot[32];
    int c = (tid < NB) ? g_blocksum[tid] : 0;
    int v = c;
#pragma unroll
    for (int o = 1; o < 32; o <<= 1) {
        int t = __shfl_up_sync(0xffffffffu, v, o);
        if (lane >= o) v += t;
    }
    if (lane == 31) wtot[w] = v;
    __syncthreads();
    if (w == 0) {
        int s = wtot[lane];
#pragma unroll
        for (int o = 1; o < 32; o <<= 1) {
            int t = __shfl_up_sync(0xffffffffu, s, o);
            if (lane >= o) s += t;
        }
        wtot[lane] = s;
    }
    __syncthreads();
    int excl = ((w == 0) ? 0 : wtot[w - 1]) + v - c;
    if (tid < NB) g_blockoff[tid] = excl;
}

__global__ __launch_bounds__(256)
void scan3_kernel(int N, int E) {
    const int tid = threadIdx.x, lane = tid & 31, w = tid >> 5;
    __shared__ int wtot[8];
    int i = blockIdx.x * 256 + tid;
    int c = (i < N) ? g_count[i] : 0;
    int v = c;
#pragma unroll
    for (int o = 1; o < 32; o <<= 1) {
        int t = __shfl_up_sync(0xffffffffu, v, o);
        if (lane >= o) v += t;
    }
    if (lane == 31) wtot[w] = v;
    __syncthreads();
    if (w == 0 && lane < 8) {
        int s = wtot[lane];
#pragma unroll
        for (int o = 1; o < 8; o <<= 1) {
            int t = __shfl_up_sync(0x000000ffu, s, o);
            if (lane >= o) s += t;
        }
        wtot[lane] = s;
    }
    __syncthreads();
    int excl = g_blockoff[blockIdx.x] + ((w == 0) ? 0 : wtot[w - 1]) + v - c;
    if (i < N) {
        g_offset[i] = excl;
        g_cursor[i] = excl;
    }
    if (i == 0) g_offset[N] = E;
}

// ---------------------------------------------------------------------------
// Scatter: write {src, eid} into dst bucket. One 8B random store per edge.
// ---------------------------------------------------------------------------
__global__ __launch_bounds__(256)
void scatter_kernel(const void* __restrict__ ei, int E) {
    const int is64 = g_is64;
    int e = blockIdx.x * blockDim.x + threadIdx.x;
    if (e >= E) return;
    int dst = load_idx(ei, is64, e);
    int src = load_idx(ei, is64, (size_t)E + e);
    int pos = atomicAdd(&g_cursor[dst], 1);
    g_se[pos] = make_int2(src, e);
}

// ---------------------------------------------------------------------------
// K1: fused node GEMM. Tile = 64 nodes x 256 outputs (128 y_neg | 128 root).
// ---------------------------------------------------------------------------
__global__ __launch_bounds__(256, 2)
void node_gemm_kernel(const float* __restrict__ x,
                      const float* __restrict__ gs,
                      const float* __restrict__ W_neg,   // [139][128]
                      const float* __restrict__ b_neg,
                      const float* __restrict__ W_root,  // [133][128]
                      const float* __restrict__ b_root,
                      float* __restrict__ out,
                      int N)
{
    __shared__ float As[64][136];
    const int tid = threadIdx.x;
    const int n0 = blockIdx.x * 64;

    for (int i = tid; i < 64 * 133; i += 256) {
        int m = i / 133;
        int k = i - m * 133;
        int n = n0 + m;
        float v = 0.0f;
        if (n < N) v = (k < 128) ? x[(size_t)n * 128 + k]
                                 : gs[(size_t)n * 5 + (k - 128)];
        As[m][k] = v;
    }
    __syncthreads();

    const int c = tid & 31;
    const int r = tid >> 5;
    const bool isRoot = (c >= 16);
    const float* Wsel = isRoot ? W_root : W_neg;
    const float* bsel = isRoot ? b_root : b_neg;
    const int cb = (isRoot ? (c - 16) : c) * 8;

    float acc[8][8];
#pragma unroll
    for (int j = 0; j < 8; j++) {
        float bv = __ldg(bsel + cb + j);
#pragma unroll
        for (int i = 0; i < 8; i++) acc[i][j] = bv;
    }

#pragma unroll 2
    for (int k = 0; k < 133; k++) {
        float4 b0 = __ldg((const float4*)(Wsel + (size_t)k * 128 + cb));
        float4 b1 = __ldg((const float4*)(Wsel + (size_t)k * 128 + cb + 4));
        float a[8];
#pragma unroll
        for (int i = 0; i < 8; i++) a[i] = As[r * 8 + i][k];
#pragma unroll
        for (int i = 0; i < 8; i++) {
            acc[i][0] += a[i] * b0.x;
            acc[i][1] += a[i] * b0.y;
            acc[i][2] += a[i] * b0.z;
            acc[i][3] += a[i] * b0.w;
            acc[i][4] += a[i] * b1.x;
            acc[i][5] += a[i] * b1.y;
            acc[i][6] += a[i] * b1.z;
            acc[i][7] += a[i] * b1.w;
        }
    }

#pragma unroll
    for (int i = 0; i < 8; i++) {
        int n = n0 + r * 8 + i;
        if (n < N) {
            if (isRoot) {
                float4 o0, o1;
                o0.x = eluf(acc[i][0]); o0.y = eluf(acc[i][1]);
                o0.z = eluf(acc[i][2]); o0.w = eluf(acc[i][3]);
                o1.x = eluf(acc[i][4]); o1.y = eluf(acc[i][5]);
                o1.z = eluf(acc[i][6]); o1.w = eluf(acc[i][7]);
                *((float4*)(out + (size_t)n * 128 + cb))     = o0;
                *((float4*)(out + (size_t)n * 128 + cb + 4)) = o1;
            } else {
                *((float4*)(g_yneg + (size_t)n * 128 + cb)) =
                    make_float4(acc[i][0], acc[i][1], acc[i][2], acc[i][3]);
                *((float4*)(g_yneg + (size_t)n * 128 + cb + 4)) =
                    make_float4(acc[i][4], acc[i][5], acc[i][6], acc[i][7]);
            }
        }
    }
}

// ---------------------------------------------------------------------------
// Gather: one warp per node, unroll x4. Per edge: int2 stream load, 3x float2
// ea load (8B-aligned: stride 24B), one dependent random 512B y_neg row load.
// ---------------------------------------------------------------------------
__global__ __launch_bounds__(256)
void gather_kernel(const float* __restrict__ W_neg,      // [139][128]
                   const float* __restrict__ edge_attr,  // [E][6]
                   float* __restrict__ out, int N)
{
    const int lane = threadIdx.x & 31;
    const int warp = blockIdx.x * (blockDim.x >> 5) + (threadIdx.x >> 5);
    if (warp >= N) return;
    const int n = warp;

    float4 w2[6];
#pragma unroll
    for (int d = 0; d < 6; d++)
        w2[d] = __ldg((const float4*)(W_neg + (size_t)(133 + d) * 128) + lane);

    const int beg = __ldg(&g_offset[n]);
    const int end = __ldg(&g_offset[n + 1]);
    float4 acc = make_float4(0.f, 0.f, 0.f, 0.f);

    int j = beg;
    for (; j + 4 <= end; j += 4) {
        int2   se[4];
        float4 v[4];
        float2 a01[4], a23[4], a45[4];
#pragma unroll
        for (int u = 0; u < 4; u++) se[u] = __ldg(&g_se[j + u]);
#pragma unroll
        for (int u = 0; u < 4; u++)
            v[u] = __ldg((const float4*)(g_yneg + (size_t)se[u].x * 128) + lane);
#pragma unroll
        for (int u = 0; u < 4; u++) {
            const float2* ea = (const float2*)(edge_attr + (size_t)se[u].y * 6);
            a01[u] = __ldg(ea + 0);
            a23[u] = __ldg(ea + 1);
            a45[u] = __ldg(ea + 2);
        }
#pragma unroll
        for (int u = 0; u < 4; u++) {
            v[u].x += a01[u].x * w2[0].x + a01[u].y * w2[1].x + a23[u].x * w2[2].x
                    + a23[u].y * w2[3].x + a45[u].x * w2[4].x + a45[u].y * w2[5].x;
            v[u].y += a01[u].x * w2[0].y + a01[u].y * w2[1].y + a23[u].x * w2[2].y
                    + a23[u].y * w2[3].y + a45[u].x * w2[4].y + a45[u].y * w2[5].y;
            v[u].z += a01[u].x * w2[0].z + a01[u].y * w2[1].z + a23[u].x * w2[2].z
                    + a23[u].y * w2[3].z + a45[u].x * w2[4].z + a45[u].y * w2[5].z;
            v[u].w += a01[u].x * w2[0].w + a01[u].y * w2[1].w + a23[u].x * w2[2].w
                    + a23[u].y * w2[3].w + a45[u].x * w2[4].w + a45[u].y * w2[5].w;
            acc.x += eluf(v[u].x);
            acc.y += eluf(v[u].y);
            acc.z += eluf(v[u].z);
            acc.w += eluf(v[u].w);
        }
    }
    for (; j < end; j++) {
        int2 se = __ldg(&g_se[j]);
        float4 v = __ldg((const float4*)(g_yneg + (size_t)se.x * 128) + lane);
        const float2* ea = (const float2*)(edge_attr + (size_t)se.y * 6);
        float2 a01 = __ldg(ea + 0);
        float2 a23 = __ldg(ea + 1);
        float2 a45 = __ldg(ea + 2);
        v.x += a01.x * w2[0].x + a01.y * w2[1].x + a23.x * w2[2].x
             + a23.y * w2[3].x + a45.x * w2[4].x + a45.y * w2[5].x;
        v.y += a01.x * w2[0].y + a01.y * w2[1].y + a23.x * w2[2].y
             + a23.y * w2[3].y + a45.x * w2[4].y + a45.y * w2[5].y;
        v.z += a01.x * w2[0].z + a01.y * w2[1].z + a23.x * w2[2].z
             + a23.y * w2[3].z + a45.x * w2[4].z + a45.y * w2[5].z;
        v.w += a01.x * w2[0].w + a01.y * w2[1].w + a23.x * w2[2].w
             + a23.y * w2[3].w + a45.x * w2[4].w + a45.y * w2[5].w;
        acc.x += eluf(v.x);
        acc.y += eluf(v.y);
        acc.z += eluf(v.z);
        acc.w += eluf(v.w);
    }

    float4* o = (float4*)(out + (size_t)n * 128) + lane;
    float4 cur = *o;
    cur.x += acc.x; cur.y += acc.y; cur.z += acc.z; cur.w += acc.w;
    *o = cur;
}

// ---------------------------------------------------------------------------
extern "C" void kernel_launch(void* const* d_in, const int* in_sizes, int n_in,
                              void* d_out, int out_size)
{
    const float* x      = (const float*)d_in[0];
    const void*  ei     = d_in[1];
    const float* eattr  = (const float*)d_in[2];
    const float* gs     = (const float*)d_in[3];
    const float* W_neg  = (const float*)d_in[4];
    const float* b_neg  = (const float*)d_in[5];
    const float* W_root = (const float*)d_in[6];
    const float* b_root = (const float*)d_in[7];
    float* out = (float*)d_out;

    const int N  = in_sizes[0] / 128;   // 100000
    const int E  = in_sizes[2] / 6;     // 1600000
    const int NB = (N + 255) / 256;

    prep_kernel<<<128, 256>>>((const int*)ei, in_sizes[1], N);
    hist_kernel<<<(E + 255) / 256, 256>>>(ei, E);
    scan1_kernel<<<NB, 256>>>(N);
    scan2_kernel<<<1, 1024>>>(NB);
    scan3_kernel<<<NB, 256>>>(N, E);
    scatter_kernel<<<(E + 255) / 256, 256>>>(ei, E);

    node_gemm_kernel<<<(N + 63) / 64, 256>>>(x, gs, W_neg, b_neg,
                                             W_root, b_root, out, N);

    gather_kernel<<<(N * 32 + 255) / 256, 256>>>(W_neg, eattr, out, N);
}